// round 1
// baseline (speedup 1.0000x reference)
#include <cuda_runtime.h>
#include <cuda_fp16.h>
#include <mma.h>

using namespace nvcuda;

#define HIDDEN   192
#define IN2      384          // 2*HIDDEN
#define NNODES   262144
#define NEDGES   262144
#define NSEG     16384
#define DEG      16

// ---------------- scratch (static device globals; no allocs allowed) --------
__device__ __half g_X[(size_t)NNODES * HIDDEN];      // node embeddings, fp16
__device__ __half g_W1h[IN2 * IN2];
__device__ __half g_W2h[IN2 * HIDDEN];
__device__ __half g_W3h[HIDDEN * HIDDEN];

// ---------------- kernel 1: sincos embedding --------------------------------
// emb layout per node: for d in 0..2: [sin(p_d*w_0..31) | cos(p_d*w_0..31)]
__global__ void embed_kernel(const float* __restrict__ pos) {
    int idx = blockIdx.x * blockDim.x + threadIdx.x;
    if (idx >= NNODES * HIDDEN) return;
    int n = idx / HIDDEN;
    int c = idx - n * HIDDEN;
    int d = c >> 6;            // c / 64
    int r = c & 63;
    int j = r & 31;
    // omega_j = 10000^(-j/32) = exp2(-j * log2(10000)/32)
    float omega = exp2f(-(float)j * (13.287712379549449f / 32.0f));
    float v = pos[n * 3 + d] * omega;
    float s = (r < 32) ? sinf(v) : cosf(v);
    g_X[idx] = __float2half(s);
}

// ---------------- kernel 2: weight convert fp32 -> fp16 ---------------------
__global__ void wconv_kernel(const float* __restrict__ W1,
                             const float* __restrict__ W2,
                             const float* __restrict__ W3) {
    int i = blockIdx.x * blockDim.x + threadIdx.x;
    if (i < IN2 * IN2)    g_W1h[i] = __float2half(W1[i]);
    if (i < IN2 * HIDDEN) g_W2h[i] = __float2half(W2[i]);
    if (i < HIDDEN * HIDDEN) g_W3h[i] = __float2half(W3[i]);
}

// ---------------- kernel 3: fused edge MLP + segment mean -------------------
// Per CTA: 128 edge rows = 8 segments of 16 contiguous edges.
// SMEM plan (bytes):
//   [0      .. 100352)  sH0: half[128][392]  (layer1 input; later sH2 half[128][200])
//   [100352 .. 200704)  sH1: half[128][392]  (layer1 out;  later sY float[128][196])
//   [200704 .. 214016)  sW : half[64][104]   (weight K-slice staging)
//   [214016 .. 224256)  sScr: per-warp float[16][20] epilogue staging (8 warps)
//   [224256 .. 225280)  sIdx: int[128*2] edge indices
#define SMEM_BYTES 225280
#define H0S 392
#define H2S 200
#define YS  196
#define WS  104

__device__ __forceinline__ float gelu_exact(float x) {
    return 0.5f * x * (1.0f + erff(x * 0.70710678118654752f));
}

template<int KDIM, int NDIMW, bool GELU, bool TOHALF>
__device__ __forceinline__ void layer_gemm(
    const __half* __restrict__ inBuf, int inStride,
    const __half* __restrict__ Wg, const float* __restrict__ bias,
    __half* __restrict__ outH, int outStride,
    float* __restrict__ outF, int outFStride,
    __half* __restrict__ sW, float* __restrict__ sScr, int tid)
{
    const int warp  = tid >> 5;
    const int lane  = tid & 31;
    const int warpM = warp & 3;   // 4 warps over M (32 rows each)
    const int warpN = warp >> 2;  // 2 warps over N (48 cols each within 96 chunk)
    float* scr = sScr + warp * 16 * 20;

    const int NCH = NDIMW / 96;
    const int KCH = KDIM / 64;

    for (int nc = 0; nc < NCH; nc++) {
        const int n0 = nc * 96;
        wmma::fragment<wmma::accumulator, 16, 16, 16, float> acc[2][3];
        #pragma unroll
        for (int i = 0; i < 2; i++)
            #pragma unroll
            for (int j = 0; j < 3; j++)
                wmma::fill_fragment(acc[i][j], 0.0f);

        for (int kc = 0; kc < KCH; kc++) {
            const int k0 = kc * 64;
            __syncthreads();   // sW safe to overwrite
            // stage W[k0:k0+64, n0:n0+96) -> sW[64][104]; 12 uint4 per row
            #pragma unroll 1
            for (int i = tid; i < 64 * 12; i += 256) {
                int kk = i / 12, q = i - kk * 12;
                *((uint4*)(sW + kk * WS) + q) =
                    *((const uint4*)(Wg + (size_t)(k0 + kk) * NDIMW + n0) + q);
            }
            __syncthreads();
            #pragma unroll
            for (int k16 = 0; k16 < 4; k16++) {
                wmma::fragment<wmma::matrix_a, 16, 16, 16, __half, wmma::row_major> a[2];
                #pragma unroll
                for (int i = 0; i < 2; i++)
                    wmma::load_matrix_sync(a[i],
                        inBuf + (warpM * 32 + i * 16) * inStride + k0 + k16 * 16,
                        inStride);
                #pragma unroll
                for (int j = 0; j < 3; j++) {
                    wmma::fragment<wmma::matrix_b, 16, 16, 16, __half, wmma::row_major> b;
                    wmma::load_matrix_sync(b, sW + (k16 * 16) * WS + warpN * 48 + j * 16, WS);
                    #pragma unroll
                    for (int i = 0; i < 2; i++)
                        wmma::mma_sync(acc[i][j], a[i], b, acc[i][j]);
                }
            }
        }
        // epilogue: per-warp fragment staging -> bias -> (gelu) -> write
        #pragma unroll
        for (int i = 0; i < 2; i++) {
            #pragma unroll
            for (int j = 0; j < 3; j++) {
                wmma::store_matrix_sync(scr, acc[i][j], 20, wmma::mem_row_major);
                __syncwarp();
                const int rowB = warpM * 32 + i * 16;
                const int colB = n0 + warpN * 48 + j * 16;
                #pragma unroll
                for (int t = lane; t < 256; t += 32) {
                    int r = t >> 4, c = t & 15;
                    float v = scr[r * 20 + c] + bias[colB + c];
                    if (GELU) v = gelu_exact(v);
                    if (TOHALF)
                        outH[(rowB + r) * outStride + colB + c] = __float2half(v);
                    else
                        outF[(rowB + r) * outFStride + colB + c] = v;
                }
                __syncwarp();
            }
        }
    }
    __syncthreads();
}

__global__ __launch_bounds__(256, 1)
void mlp_kernel(const int* __restrict__ edges,
                const float* __restrict__ b1,
                const float* __restrict__ b2,
                const float* __restrict__ b3,
                float* __restrict__ out)
{
    extern __shared__ char smem[];
    __half* sH0  = (__half*)(smem);
    __half* sH1  = (__half*)(smem + 100352);
    __half* sH2  = (__half*)(smem);            // reuses sH0 region
    float*  sY   = (float*)(smem + 100352);    // reuses sH1 region
    __half* sW   = (__half*)(smem + 200704);
    float*  sScr = (float*)(smem + 214016);
    int*    sIdx = (int*)(smem + 224256);

    const int tid = threadIdx.x;
    const int e0  = blockIdx.x * 128;

    // edge indices for this tile: [dst, src] pairs
    for (int i = tid; i < 256; i += 256) sIdx[i] = edges[e0 * 2 + i];
    __syncthreads();

    // gather: row = [ x[src] (192) | x[dst] (192) ], 48 uint4 per row
    #pragma unroll 1
    for (int i = tid; i < 128 * 48; i += 256) {
        int row = i / 48, q = i - row * 48;
        int isDst = (q >= 24);
        int node  = sIdx[row * 2 + (isDst ? 0 : 1)];
        int qq    = isDst ? (q - 24) : q;
        uint4 v = *((const uint4*)(g_X + (size_t)node * HIDDEN) + qq);
        *((uint4*)(sH0 + row * H0S + (isDst ? HIDDEN : 0)) + qq) = v;
    }
    __syncthreads();

    // layer 1: [128,384]@[384,384] + b1, gelu  -> sH1 (fp16)
    layer_gemm<IN2, IN2, true, true>(sH0, H0S, g_W1h, b1, sH1, H0S, nullptr, 0, sW, sScr, tid);
    // layer 2: [128,384]@[384,192] + b2, gelu  -> sH2 (fp16, in sH0 region)
    layer_gemm<IN2, HIDDEN, true, true>(sH1, H0S, g_W2h, b2, sH2, H2S, nullptr, 0, sW, sScr, tid);
    // layer 3: [128,192]@[192,192] + b3        -> sY (fp32, in sH1 region)
    layer_gemm<HIDDEN, HIDDEN, false, false>(sH2, H2S, g_W3h, b3, nullptr, 0, sY, YS, sW, sScr, tid);

    // segment mean: 8 segments x 16 rows -> out[seg][192]
    const int seg0 = blockIdx.x * 8;
    #pragma unroll 1
    for (int i = tid; i < 8 * HIDDEN; i += 256) {
        int s = i / HIDDEN, c = i - s * HIDDEN;
        float acc = 0.0f;
        #pragma unroll
        for (int r = 0; r < DEG; r++) acc += sY[(s * DEG + r) * YS + c];
        out[(size_t)(seg0 + s) * HIDDEN + c] = acc * (1.0f / 16.0f);
    }
}

// ---------------- launch ----------------------------------------------------
extern "C" void kernel_launch(void* const* d_in, const int* in_sizes, int n_in,
                              void* d_out, int out_size) {
    const float* mesh_pos   = (const float*)d_in[0];
    const int*   mesh_edges = (const int*)d_in[1];
    // d_in[2] = batch_idx (unused by the reference computation)
    const float* W1 = (const float*)d_in[3];
    const float* b1 = (const float*)d_in[4];
    const float* W2 = (const float*)d_in[5];
    const float* b2 = (const float*)d_in[6];
    const float* W3 = (const float*)d_in[7];
    const float* b3 = (const float*)d_in[8];
    float* out = (float*)d_out;

    cudaFuncSetAttribute(mlp_kernel, cudaFuncAttributeMaxDynamicSharedMemorySize, SMEM_BYTES);

    embed_kernel<<<(NNODES * HIDDEN + 255) / 256, 256>>>(mesh_pos);
    wconv_kernel<<<(IN2 * IN2 + 255) / 256, 256>>>(W1, W2, W3);
    mlp_kernel<<<NEDGES / 128, 256, SMEM_BYTES>>>(mesh_edges, b1, b2, b3, out);
}